// round 11
// baseline (speedup 1.0000x reference)
#include <cuda_runtime.h>
#include <cuda_bf16.h>
#include <cstdint>

// Elementwise hard clip: out[i] = clamp(x[i], -0.5f, 0.5f)
// N = 67,108,864 fp32. 2048 CTAs x 256 threads, 128KB contiguous tile per CTA.
// Software-pipelined: prefetch the next group of 4 x 256-bit loads while
// clipping/storing the current group, so the read stream never drains
// during the write phase. Group = 4 x v8 = 32KB per CTA phase.

#define CLIP_LO (-0.5f)
#define CLIP_HI (0.5f)
#define GRP 4   // 4 x 32B = 128B per thread per group

struct f8 { float v[8]; };

__device__ __forceinline__ f8 ld256cs(const float* p) {
    f8 r;
    asm volatile(
        "ld.global.cs.v8.f32 {%0,%1,%2,%3,%4,%5,%6,%7}, [%8];"
        : "=f"(r.v[0]), "=f"(r.v[1]), "=f"(r.v[2]), "=f"(r.v[3]),
          "=f"(r.v[4]), "=f"(r.v[5]), "=f"(r.v[6]), "=f"(r.v[7])
        : "l"(p));
    return r;
}

__device__ __forceinline__ void st256cs(float* p, const f8& r) {
    asm volatile(
        "st.global.cs.v8.f32 [%0], {%1,%2,%3,%4,%5,%6,%7,%8};"
        :: "l"(p),
           "f"(r.v[0]), "f"(r.v[1]), "f"(r.v[2]), "f"(r.v[3]),
           "f"(r.v[4]), "f"(r.v[5]), "f"(r.v[6]), "f"(r.v[7])
        : "memory");
}

__device__ __forceinline__ void clip8(f8& a) {
#pragma unroll
    for (int k = 0; k < 8; k++)
        a.v[k] = fminf(fmaxf(a.v[k], CLIP_LO), CLIP_HI);
}

// Each CTA owns a contiguous tile [start, start+chunk) in float8 (32B) units.
// Pipelined loop: load group g+1, then clip+store group g.
__global__ __launch_bounds__(256) void clip_kernel_pipe(
    const float* __restrict__ in, float* __restrict__ out,
    int n8, int chunk)
{
    const int bdim = blockDim.x;
    int start = blockIdx.x * chunk;
    int end = start + chunk;
    if (end > n8) end = n8;

    int i = start + threadIdx.x;
    const int step = bdim * GRP;

    if (i + (GRP - 1) * bdim < end) {
        // Prologue: load first group.
        f8 cur[GRP];
#pragma unroll
        for (int j = 0; j < GRP; j++)
            cur[j] = ld256cs(in + (size_t)(i + j * bdim) * 8);

        int ip = i;          // position of 'cur'
        i += step;
        // Steady state: prefetch next group before draining current one.
        for (; i + (GRP - 1) * bdim < end; i += step) {
            f8 nxt[GRP];
#pragma unroll
            for (int j = 0; j < GRP; j++)
                nxt[j] = ld256cs(in + (size_t)(i + j * bdim) * 8);
#pragma unroll
            for (int j = 0; j < GRP; j++)
                clip8(cur[j]);
#pragma unroll
            for (int j = 0; j < GRP; j++)
                st256cs(out + (size_t)(ip + j * bdim) * 8, cur[j]);
#pragma unroll
            for (int j = 0; j < GRP; j++)
                cur[j] = nxt[j];
            ip = i;
        }
        // Epilogue: drain last group.
#pragma unroll
        for (int j = 0; j < GRP; j++)
            clip8(cur[j]);
#pragma unroll
        for (int j = 0; j < GRP; j++)
            st256cs(out + (size_t)(ip + j * bdim) * 8, cur[j]);
    }
    // Remainder within the tile (sub-GRP iterations; not hit for this N).
    for (; i < end; i += bdim) {
        f8 a = ld256cs(in + (size_t)i * 8);
        clip8(a);
        st256cs(out + (size_t)i * 8, a);
    }
}

// Scalar tail for N not divisible by 8 (not hit for this problem's N).
__global__ void clip_kernel_tail(
    const float* __restrict__ in, float* __restrict__ out, int start, int n)
{
    int i = start + blockIdx.x * blockDim.x + threadIdx.x;
    if (i < n) {
        out[i] = fminf(fmaxf(__ldcs(in + i), CLIP_LO), CLIP_HI);
    }
}

extern "C" void kernel_launch(void* const* d_in, const int* in_sizes, int n_in,
                              void* d_out, int out_size)
{
    const float* x = (const float*)d_in[0];
    float* out = (float*)d_out;
    int n = in_sizes[0];

    int n8 = n / 8;
    const int threads = 256;

    // 2048 CTAs: for n8 = 2^23, chunk = 4096 float8 = 128KB contiguous per CTA
    // (4 pipelined groups of 1024 float8 = 32KB each).
    int blocks = 2048;
    int chunk = (n8 + blocks - 1) / blocks;
    chunk = ((chunk + threads - 1) / threads) * threads;
    blocks = (n8 + chunk - 1) / chunk;
    if (blocks < 1) { blocks = 1; chunk = n8 > 0 ? n8 : 1; }

    clip_kernel_pipe<<<blocks, threads>>>(x, out, n8, chunk);

    int tail_start = n8 * 8;
    int tail = n - tail_start;
    if (tail > 0) {
        clip_kernel_tail<<<(tail + 255) / 256, 256>>>(x, out, tail_start, n);
    }
}